// round 10
// baseline (speedup 1.0000x reference)
#include <cuda_runtime.h>
#include <cuda_fp16.h>
#include <math.h>

#define NN 100000
#define EE 1600000
#define CH 64      // NHID
#define NF 128     // NFEAT
#define NC 40      // NCLASS
#define SCAN_B 1024
#define NB_SCAN ((NN + SCAN_B - 1) / SCAN_B)   // 98
#define NPB 96     // rows per fused block
#define MMR 96     // rows per mm0 block
#define FILLB ((EE + 255) / 256)               // 6250
#define MMB0  ((NN + MMR - 1) / MMR)           // 1042

typedef unsigned long long ull;

// ---- packed f32x2 helpers (sm_10x FFMA2; PTX-only) ----
__device__ __forceinline__ ull pk2(float lo, float hi) {
    ull r;
    asm("mov.b64 %0, {%1, %2};" : "=l"(r) : "r"(__float_as_uint(lo)), "r"(__float_as_uint(hi)));
    return r;
}
__device__ __forceinline__ void upk2(ull v, float& lo, float& hi) {
    unsigned a, b;
    asm("mov.b64 {%0, %1}, %2;" : "=r"(a), "=r"(b) : "l"(v));
    lo = __uint_as_float(a); hi = __uint_as_float(b);
}
__device__ __forceinline__ ull fma2(ull a, ull b, ull c) {
    ull d;
    asm("fma.rn.f32x2 %0, %1, %2, %3;" : "=l"(d) : "l"(a), "l"(b), "l"(c));
    return d;
}

// ---- scratch (static device globals; no allocation) ----
__device__ float  g_h[NN * CH];
__device__ float  g_acc[NN * CH];
__device__ float  g_s[2][NN * CH];    // fp32 double-buffered gather source
__device__ float  g_sf[NN * CH];      // fp32 final-logits buffer
__device__ int    g_rowptr[NN + 1];
__device__ int    g_cursor[NN];
__device__ int    g_cnt[NN];          // zero at module load; re-zeroed by k_prep each call
__device__ int2   g_edgep[EE];        // packed {src, w-bits}

// ============================ CSR build ============================
__global__ void k_hist(const int* __restrict__ tgt) {
    int e = blockIdx.x * blockDim.x + threadIdx.x;
    if (e < EE) atomicAdd(&g_cnt[tgt[e]], 1);
}

// one-kernel scan: each block reduces its global prefix from g_cnt, then local scan
__global__ void k_scan_all() {
    __shared__ int sh[SCAN_B];
    __shared__ int soff;
    int b = blockIdx.x, tid = threadIdx.x;
    int base = b * SCAN_B;
    int acc = 0;
    for (int j = tid; j < base; j += SCAN_B) acc += g_cnt[j];
    sh[tid] = acc;
    __syncthreads();
    for (int d = SCAN_B / 2; d; d >>= 1) {
        if (tid < d) sh[tid] += sh[tid + d];
        __syncthreads();
    }
    if (tid == 0) soff = sh[0];
    __syncthreads();
    int i = base + tid;
    int v = (i < NN) ? g_cnt[i] : 0;
    sh[tid] = v;
    __syncthreads();
    for (int d = 1; d < SCAN_B; d <<= 1) {
        int t = (tid >= d) ? sh[tid - d] : 0;
        __syncthreads();
        sh[tid] += t;
        __syncthreads();
    }
    if (i < NN) {
        int ex = soff + sh[tid] - v;
        g_rowptr[i] = ex;
        g_cursor[i] = ex;
    }
    if (b == NB_SCAN - 1 && tid == SCAN_B - 1) g_rowptr[NN] = soff + sh[tid];
}

// ================= prep: CSR fill + mm0 dense + cnt re-zero (merged) =================
__global__ void k_prep(const float* __restrict__ x,
                       const int* __restrict__ src, const int* __restrict__ tgt,
                       const float* __restrict__ w,
                       const float* __restrict__ W0, const float* __restrict__ b0) {
    __shared__ float Wsh[NF * CH];   // 32KB (only used by mm0 blocks)
    int tid = threadIdx.x;

    if (blockIdx.x < FILLB) {
        int e = blockIdx.x * 256 + tid;
        if (e < EE) {
            int slot = atomicAdd(&g_cursor[tgt[e]], 1);
            g_edgep[slot] = make_int2(src[e], __float_as_int(w[e]));
        }
        return;
    }

    int mb = blockIdx.x - FILLB;     // 0..MMB0-1
    for (int i = mb * 256 + tid; i < NN; i += MMB0 * 256) g_cnt[i] = 0;

    for (int i = tid; i < NF * CH; i += 256) Wsh[i] = W0[i];
    __syncthreads();

    int base = mb * MMR;
    int ty = tid >> 4, tx = tid & 15;
    int c0 = tx * 4;

    ull a01[6], a23[6];
    ull b01 = pk2(b0[c0], b0[c0 + 1]), b23 = pk2(b0[c0 + 2], b0[c0 + 3]);
#pragma unroll
    for (int i = 0; i < 6; i++) { a01[i] = b01; a23[i] = b23; }

    const float* xr[6];
#pragma unroll
    for (int i = 0; i < 6; i++) {
        int nd = base + ty + 16 * i;
        if (nd > NN - 1) nd = NN - 1;
        xr[i] = x + (size_t)nd * NF;
    }
    for (int k = 0; k < NF; k += 4) {
        float4 a4[6];
#pragma unroll
        for (int i = 0; i < 6; i++) a4[i] = *(const float4*)&xr[i][k];
#pragma unroll
        for (int kk = 0; kk < 4; kk++) {
            float4 w4 = *(const float4*)&Wsh[(k + kk) * CH + c0];
            ull w01 = pk2(w4.x, w4.y), w23 = pk2(w4.z, w4.w);
#pragma unroll
            for (int i = 0; i < 6; i++) {
                float a = (kk == 0) ? a4[i].x : (kk == 1) ? a4[i].y : (kk == 2) ? a4[i].z : a4[i].w;
                ull aa = pk2(a, a);
                a01[i] = fma2(aa, w01, a01[i]);
                a23[i] = fma2(aa, w23, a23[i]);
            }
        }
    }
#pragma unroll
    for (int i = 0; i < 6; i++) {
        int nd = base + ty + 16 * i;
        if (nd < NN) {
            float v0, v1, v2, v3;
            upk2(a01[i], v0, v1); upk2(a23[i], v2, v3);
            *(float4*)&g_s[0][nd * CH + c0] = make_float4(v0, v1, v2, v3);
        }
    }
}

// ================= fused SpMM + RK4 bookkeeping + groupnorm + dense =================
// Gather now uses warp-uniform LDG.64 of packed edges (1 broadcast wavefront each)
// instead of stage+16xSHFL — cuts MIO pipe pressure ~27% in phase 1.
//   mode 0: h = k, store g_h;                heff = h
//   mode 1: acc  = wk*k;                     heff = h + ch*k
//   mode 2: acc += wk*k;                     heff = h + ch*k
//   mode 4: h  += acc + wk*k, store g_h;     heff = h_new
//   mode 5: as 4, but phase 2 uses W2, no groupnorm, out to g_sf
__global__ void __launch_bounds__(256, 5)
k_fused(int mode, int pin, float wk, float ch, float tval,
        const float* __restrict__ W1, const float* __restrict__ b1,
        const float* __restrict__ gnw, const float* __restrict__ gnb,
        const float* __restrict__ W2, const float* __restrict__ b2) {
    __shared__ float Wsh[65 * CH];     // 16.25 KB
    __shared__ float bsh[CH];
    __shared__ float hsh[NPB * 66];    // 24.75 KB

    const float* __restrict__ sin = g_s[pin];

    int tid = threadIdx.x;
    if (mode < 5) {
        for (int i = tid; i < 65 * CH; i += 256) Wsh[i] = W1[i];
        if (tid < CH) bsh[tid] = b1[tid];
    } else {
        for (int i = tid; i < 65 * CH; i += 256) {
            int r = i >> 6, c = i & 63;
            Wsh[i] = (r >= 1 && c < NC) ? W2[(r - 1) * NC + c] : 0.f;
        }
        if (tid < CH) bsh[tid] = (tid < NC) ? b2[tid] : 0.f;
    }

    int wid = tid >> 5, lane = tid & 31;
    int base = blockIdx.x * NPB;

    float gw0 = 0.f, gw1 = 0.f, gb0 = 0.f, gb1 = 0.f;
    if (mode < 5) {
        gw0 = gnw[2 * lane];     gw1 = gnw[2 * lane + 1];
        gb0 = gnb[2 * lane];     gb1 = gnb[2 * lane + 1];
    }

    // Phase 1: each warp handles 12 rows; lane covers column pair (2l, 2l+1)
    for (int r = 0; r < NPB / 8; r++) {
        int lr  = wid * (NPB / 8) + r;
        int row = base + lr;
        float ax = 0.f, ay = 0.f;
        if (row < NN) {
            int beg = g_rowptr[row], end = g_rowptr[row + 1];
            for (int e = beg; e < end; e += 8) {
                int sidx[8]; float ww[8];
#pragma unroll
                for (int u = 0; u < 8; u++) {
                    int ix = e + u;
                    bool vld = ix < end;
                    int2 ed = g_edgep[vld ? ix : beg];   // warp-uniform broadcast load
                    sidx[u] = ed.x;
                    ww[u]   = vld ? __int_as_float(ed.y) : 0.f;
                }
                float2 rr[8];
#pragma unroll
                for (int u = 0; u < 8; u++)
                    rr[u] = *(const float2*)&sin[sidx[u] * CH + 2 * lane];
#pragma unroll
                for (int u = 0; u < 8; u++) {
                    ax += ww[u] * rr[u].x;
                    ay += ww[u] * rr[u].y;
                }
            }
        }
        float vx = fmaxf(ax, 0.f), vy = fmaxf(ay, 0.f);  // k
        float hx = 0.f, hy = 0.f;                        // heff
        if (row < NN) {
            int o = row * CH + 2 * lane;
            if (mode == 0) {
                g_h[o] = vx; g_h[o + 1] = vy;
                hx = vx; hy = vy;
            } else if (mode == 1) {
                float h0 = g_h[o], h1 = g_h[o + 1];
                g_acc[o] = wk * vx; g_acc[o + 1] = wk * vy;
                hx = h0 + ch * vx; hy = h1 + ch * vy;
            } else if (mode == 2) {
                float h0 = g_h[o], h1 = g_h[o + 1];
                g_acc[o] += wk * vx; g_acc[o + 1] += wk * vy;
                hx = h0 + ch * vx; hy = h1 + ch * vy;
            } else {  // 4 or 5: k4 state update
                float h0 = g_h[o] + g_acc[o]     + wk * vx;
                float h1 = g_h[o + 1] + g_acc[o + 1] + wk * vy;
                g_h[o] = h0; g_h[o + 1] = h1;
                hx = h0; hy = h1;
            }
        }
        float gx, gy;
        if (mode < 5) {
            float d  = 0.5f * (hx - hy);
            float rr = rsqrtf(d * d + 1e-5f);
            gx =  d * rr * gw0 + gb0;
            gy = -d * rr * gw1 + gb1;
        } else {
            gx = hx; gy = hy;
        }
        hsh[lr * 66 + 1 + 2 * lane] = gx;
        hsh[lr * 66 + 2 + 2 * lane] = gy;
        if (lane == 0) hsh[lr * 66] = (mode < 5) ? tval : 0.f;
    }
    __syncthreads();

    // Phase 2: tiled dense with packed f32x2 FMA, 96 rows = 16 ty-slots x 6
    int ty = tid >> 4, tx = tid & 15;
    int c0 = tx * 4;
    ull b01 = pk2(bsh[c0], bsh[c0 + 1]), b23 = pk2(bsh[c0 + 2], bsh[c0 + 3]);
    ull a01[6], a23[6];
#pragma unroll
    for (int i = 0; i < 6; i++) { a01[i] = b01; a23[i] = b23; }
    for (int k = 0; k < 65; k++) {
        float4 w4 = *(const float4*)&Wsh[k * CH + c0];
        ull w01 = pk2(w4.x, w4.y), w23 = pk2(w4.z, w4.w);
#pragma unroll
        for (int i = 0; i < 6; i++) {
            float a = hsh[(ty + 16 * i) * 66 + k];
            ull aa = pk2(a, a);
            a01[i] = fma2(aa, w01, a01[i]);
            a23[i] = fma2(aa, w23, a23[i]);
        }
    }
    float* sout = (mode < 5) ? g_s[1 - pin] : g_sf;
#pragma unroll
    for (int i = 0; i < 6; i++) {
        int nd = base + ty + 16 * i;
        if (nd < NN) {
            float v0, v1, v2, v3;
            upk2(a01[i], v0, v1); upk2(a23[i], v2, v3);
            *(float4*)&sout[nd * CH + c0] = make_float4(v0, v1, v2, v3);
        }
    }
}

// ============ final SpMM (40 cols, fp32 source) + log_softmax ============
__global__ void k_spmm40(float* __restrict__ out) {
    int row = (blockIdx.x * blockDim.x + threadIdx.x) >> 5;
    if (row >= NN) return;
    int lane = threadIdx.x & 31;
    int beg = g_rowptr[row], end = g_rowptr[row + 1];
    float ax = 0.f, ay = 0.f;
    for (int e = beg; e < end; e += 4) {
        int sidx[4]; float ww[4];
#pragma unroll
        for (int u = 0; u < 4; u++) {
            int ix = e + u;
            bool vld = ix < end;
            int2 ed = g_edgep[vld ? ix : beg];
            sidx[u] = ed.x;
            ww[u]   = vld ? __int_as_float(ed.y) : 0.f;
        }
        if (lane < 20) {
            float2 rr[4];
#pragma unroll
            for (int u = 0; u < 4; u++)
                rr[u] = *(const float2*)&g_sf[sidx[u] * CH + 2 * lane];
#pragma unroll
            for (int u = 0; u < 4; u++) {
                ax += ww[u] * rr[u].x;
                ay += ww[u] * rr[u].y;
            }
        }
    }
    float NEG_INF = __int_as_float(0xff800000);
    float m = (lane < 20) ? fmaxf(ax, ay) : NEG_INF;
#pragma unroll
    for (int o = 16; o; o >>= 1) m = fmaxf(m, __shfl_xor_sync(0xffffffffu, m, o));
    float se = (lane < 20) ? (expf(ax - m) + expf(ay - m)) : 0.f;
#pragma unroll
    for (int o = 16; o; o >>= 1) se += __shfl_xor_sync(0xffffffffu, se, o);
    float lse = m + logf(se);
    if (lane < 20) {
        out[row * NC + 2 * lane]     = ax - lse;
        out[row * NC + 2 * lane + 1] = ay - lse;
    }
}

// =============================== driver ===============================
extern "C" void kernel_launch(void* const* d_in, const int* in_sizes, int n_in,
                              void* d_out, int out_size) {
    const float* x   = (const float*)d_in[0];
    const int*   src = (const int*)  d_in[1];
    const int*   tgt = (const int*)  d_in[2];
    const float* mw  = (const float*)d_in[3];
    const float* W0  = (const float*)d_in[4];
    const float* b0  = (const float*)d_in[5];
    const float* gnw = (const float*)d_in[6];
    const float* gnb = (const float*)d_in[7];
    const float* W1  = (const float*)d_in[8];
    const float* b1  = (const float*)d_in[9];
    const float* W2  = (const float*)d_in[10];
    const float* b2  = (const float*)d_in[11];
    float* out = (float*)d_out;
    (void)in_sizes; (void)n_in; (void)out_size;

    const int FUB = (NN + NPB - 1) / NPB;
    const int SPB = (NN * 32 + 255) / 256;

    k_hist<<<FILLB, 256>>>(tgt);                               // idx 0
    k_scan_all<<<NB_SCAN, SCAN_B>>>();                         // idx 1
    k_prep<<<FILLB + MMB0, 256>>>(x, src, tgt, mw, W0, b0);    // idx 2

    int p = 0;
    // idx 3 — ncu capture slot: fused [spmm0 + first-eval dense]
    k_fused<<<FUB, 256>>>(0, p, 0.f, 0.f, 0.0f, W1, b1, gnw, gnb, W2, b2);
    p ^= 1;

    const float dt = 0.25f;
    for (int st = 0; st < 4; st++) {
        float t0 = st * dt;
        k_fused<<<FUB, 256>>>(1, p, dt / 6.f, dt * 0.5f, t0 + dt * 0.5f, W1, b1, gnw, gnb, W2, b2); p ^= 1;
        k_fused<<<FUB, 256>>>(2, p, dt / 3.f, dt * 0.5f, t0 + dt * 0.5f, W1, b1, gnw, gnb, W2, b2); p ^= 1;
        k_fused<<<FUB, 256>>>(2, p, dt / 3.f, dt,        t0 + dt,        W1, b1, gnw, gnb, W2, b2); p ^= 1;
        int m4 = (st == 3) ? 5 : 4;
        k_fused<<<FUB, 256>>>(m4, p, dt / 6.f, 0.f, (st + 1) * dt, W1, b1, gnw, gnb, W2, b2); p ^= 1;
    }

    k_spmm40<<<SPB, 256>>>(out);
}

// round 11
// speedup vs baseline: 1.0867x; 1.0867x over previous
#include <cuda_runtime.h>
#include <cuda_fp16.h>
#include <math.h>

#define NN 100000
#define EE 1600000
#define CH 64      // NHID
#define NF 128     // NFEAT
#define NC 40      // NCLASS
#define SCAN_B 1024
#define NB_SCAN ((NN + SCAN_B - 1) / SCAN_B)   // 98
#define NPB 96     // rows per fused block (R6-proven)
#define MMR 96     // rows per mm0 block
#define FILLB ((EE + 255) / 256)               // 6250
#define MMB0  ((NN + MMR - 1) / MMR)           // 1042

typedef unsigned long long ull;

// ---- packed f32x2 helpers (sm_10x FFMA2; PTX-only) ----
__device__ __forceinline__ ull pk2(float lo, float hi) {
    ull r;
    asm("mov.b64 %0, {%1, %2};" : "=l"(r) : "r"(__float_as_uint(lo)), "r"(__float_as_uint(hi)));
    return r;
}
__device__ __forceinline__ void upk2(ull v, float& lo, float& hi) {
    unsigned a, b;
    asm("mov.b64 {%0, %1}, %2;" : "=r"(a), "=r"(b) : "l"(v));
    lo = __uint_as_float(a); hi = __uint_as_float(b);
}
__device__ __forceinline__ ull fma2(ull a, ull b, ull c) {
    ull d;
    asm("fma.rn.f32x2 %0, %1, %2, %3;" : "=l"(d) : "l"(a), "l"(b), "l"(c));
    return d;
}

// ---- scratch (static device globals; no allocation) ----
__device__ float  g_h[NN * CH];
__device__ float  g_acc[NN * CH];
__device__ float  g_s[2][NN * CH];    // fp32 double-buffered gather source
__device__ float  g_sf[NN * CH];      // fp32 final-logits buffer
__device__ int    g_rowptr[NN + 1];
__device__ int    g_cursor[NN];
__device__ int    g_cnt[NN];          // zero at module load; re-zeroed by k_prep each call
__device__ int    g_csrsrc[EE];
__device__ float  g_csrw[EE];

// ============================ CSR build ============================
__global__ void k_hist(const int* __restrict__ tgt) {
    int e = blockIdx.x * blockDim.x + threadIdx.x;
    if (e < EE) atomicAdd(&g_cnt[tgt[e]], 1);
}

// one-kernel scan: each block reduces its global prefix from g_cnt, then local scan
__global__ void k_scan_all() {
    __shared__ int sh[SCAN_B];
    __shared__ int soff;
    int b = blockIdx.x, tid = threadIdx.x;
    int base = b * SCAN_B;
    int acc = 0;
    for (int j = tid; j < base; j += SCAN_B) acc += g_cnt[j];
    sh[tid] = acc;
    __syncthreads();
    for (int d = SCAN_B / 2; d; d >>= 1) {
        if (tid < d) sh[tid] += sh[tid + d];
        __syncthreads();
    }
    if (tid == 0) soff = sh[0];
    __syncthreads();
    int i = base + tid;
    int v = (i < NN) ? g_cnt[i] : 0;
    sh[tid] = v;
    __syncthreads();
    for (int d = 1; d < SCAN_B; d <<= 1) {
        int t = (tid >= d) ? sh[tid - d] : 0;
        __syncthreads();
        sh[tid] += t;
        __syncthreads();
    }
    if (i < NN) {
        int ex = soff + sh[tid] - v;
        g_rowptr[i] = ex;
        g_cursor[i] = ex;
    }
    if (b == NB_SCAN - 1 && tid == SCAN_B - 1) g_rowptr[NN] = soff + sh[tid];
}

// ================= prep: CSR fill + mm0 dense + cnt re-zero (merged) =================
__global__ void k_prep(const float* __restrict__ x,
                       const int* __restrict__ src, const int* __restrict__ tgt,
                       const float* __restrict__ w,
                       const float* __restrict__ W0, const float* __restrict__ b0) {
    __shared__ float Wsh[NF * CH];   // 32KB (only used by mm0 blocks)
    int tid = threadIdx.x;

    if (blockIdx.x < FILLB) {
        int e = blockIdx.x * 256 + tid;
        if (e < EE) {
            int slot = atomicAdd(&g_cursor[tgt[e]], 1);
            g_csrsrc[slot] = src[e];
            g_csrw[slot]  = w[e];
        }
        return;
    }

    int mb = blockIdx.x - FILLB;     // 0..MMB0-1
    for (int i = mb * 256 + tid; i < NN; i += MMB0 * 256) g_cnt[i] = 0;

    for (int i = tid; i < NF * CH; i += 256) Wsh[i] = W0[i];
    __syncthreads();

    int base = mb * MMR;
    int ty = tid >> 4, tx = tid & 15;
    int c0 = tx * 4;

    ull a01[6], a23[6];
    ull b01 = pk2(b0[c0], b0[c0 + 1]), b23 = pk2(b0[c0 + 2], b0[c0 + 3]);
#pragma unroll
    for (int i = 0; i < 6; i++) { a01[i] = b01; a23[i] = b23; }

    const float* xr[6];
#pragma unroll
    for (int i = 0; i < 6; i++) {
        int nd = base + ty + 16 * i;
        if (nd > NN - 1) nd = NN - 1;
        xr[i] = x + (size_t)nd * NF;
    }
    for (int k = 0; k < NF; k += 4) {
        float4 a4[6];
#pragma unroll
        for (int i = 0; i < 6; i++) a4[i] = *(const float4*)&xr[i][k];
#pragma unroll
        for (int kk = 0; kk < 4; kk++) {
            float4 w4 = *(const float4*)&Wsh[(k + kk) * CH + c0];
            ull w01 = pk2(w4.x, w4.y), w23 = pk2(w4.z, w4.w);
#pragma unroll
            for (int i = 0; i < 6; i++) {
                float a = (kk == 0) ? a4[i].x : (kk == 1) ? a4[i].y : (kk == 2) ? a4[i].z : a4[i].w;
                ull aa = pk2(a, a);
                a01[i] = fma2(aa, w01, a01[i]);
                a23[i] = fma2(aa, w23, a23[i]);
            }
        }
    }
#pragma unroll
    for (int i = 0; i < 6; i++) {
        int nd = base + ty + 16 * i;
        if (nd < NN) {
            float v0, v1, v2, v3;
            upk2(a01[i], v0, v1); upk2(a23[i], v2, v3);
            *(float4*)&g_s[0][nd * CH + c0] = make_float4(v0, v1, v2, v3);
        }
    }
}

// ================= fused SpMM + RK4 bookkeeping + groupnorm + dense =================
// R6-proven body VERBATIM: padded shfl unroll-8 gather, split src/w arrays,
// NPB=96, no launch_bounds min-blocks clamp, no prefetch.
//   mode 0: h = k, store g_h;                heff = h
//   mode 1: acc  = wk*k;                     heff = h + ch*k
//   mode 2: acc += wk*k;                     heff = h + ch*k
//   mode 4: h  += acc + wk*k, store g_h;     heff = h_new
//   mode 5: as 4, but phase 2 uses W2, no groupnorm, out to g_sf
__global__ void __launch_bounds__(256)
k_fused(int mode, int pin, float wk, float ch, float tval,
        const float* __restrict__ W1, const float* __restrict__ b1,
        const float* __restrict__ gnw, const float* __restrict__ gnb,
        const float* __restrict__ W2, const float* __restrict__ b2) {
    __shared__ float Wsh[65 * CH];     // 16.25 KB
    __shared__ float bsh[CH];
    __shared__ float hsh[NPB * 66];    // 24.75 KB

    const float* __restrict__ sin = g_s[pin];

    int tid = threadIdx.x;
    if (mode < 5) {
        for (int i = tid; i < 65 * CH; i += 256) Wsh[i] = W1[i];
        if (tid < CH) bsh[tid] = b1[tid];
    } else {
        for (int i = tid; i < 65 * CH; i += 256) {
            int r = i >> 6, c = i & 63;
            Wsh[i] = (r >= 1 && c < NC) ? W2[(r - 1) * NC + c] : 0.f;
        }
        if (tid < CH) bsh[tid] = (tid < NC) ? b2[tid] : 0.f;
    }

    int wid = tid >> 5, lane = tid & 31;
    int base = blockIdx.x * NPB;

    float gw0 = 0.f, gw1 = 0.f, gb0 = 0.f, gb1 = 0.f;
    if (mode < 5) {
        gw0 = gnw[2 * lane];     gw1 = gnw[2 * lane + 1];
        gb0 = gnb[2 * lane];     gb1 = gnb[2 * lane + 1];
    }

    // Phase 1: each warp handles 12 rows; lane covers column pair (2l, 2l+1)
    for (int r = 0; r < NPB / 8; r++) {
        int lr  = wid * (NPB / 8) + r;
        int row = base + lr;
        float ax = 0.f, ay = 0.f;
        if (row < NN) {
            int beg = g_rowptr[row], end = g_rowptr[row + 1];
            for (int j = beg; j < end; j += 32) {
                int idx = j + lane;
                int sv = 0; float wv = 0.f;
                if (idx < end) { sv = g_csrsrc[idx]; wv = g_csrw[idx]; }
                int cnt8 = (min(32, end - j) + 7) & ~7;   // pad; dummy lanes sv=0, wv=0
                for (int q = 0; q < cnt8; q += 8) {
                    int ss[8]; float ww[8];
#pragma unroll
                    for (int u = 0; u < 8; u++) {
                        ss[u] = __shfl_sync(0xffffffffu, sv, q + u);
                        ww[u] = __shfl_sync(0xffffffffu, wv, q + u);
                    }
                    float2 rr[8];
#pragma unroll
                    for (int u = 0; u < 8; u++)
                        rr[u] = *(const float2*)&sin[ss[u] * CH + 2 * lane];
#pragma unroll
                    for (int u = 0; u < 8; u++) {
                        ax += ww[u] * rr[u].x;
                        ay += ww[u] * rr[u].y;
                    }
                }
            }
        }
        float vx = fmaxf(ax, 0.f), vy = fmaxf(ay, 0.f);  // k
        float hx = 0.f, hy = 0.f;                        // heff
        if (row < NN) {
            int o = row * CH + 2 * lane;
            if (mode == 0) {
                g_h[o] = vx; g_h[o + 1] = vy;
                hx = vx; hy = vy;
            } else if (mode == 1) {
                float h0 = g_h[o], h1 = g_h[o + 1];
                g_acc[o] = wk * vx; g_acc[o + 1] = wk * vy;
                hx = h0 + ch * vx; hy = h1 + ch * vy;
            } else if (mode == 2) {
                float h0 = g_h[o], h1 = g_h[o + 1];
                g_acc[o] += wk * vx; g_acc[o + 1] += wk * vy;
                hx = h0 + ch * vx; hy = h1 + ch * vy;
            } else {  // 4 or 5: k4 state update
                float h0 = g_h[o] + g_acc[o]     + wk * vx;
                float h1 = g_h[o + 1] + g_acc[o + 1] + wk * vy;
                g_h[o] = h0; g_h[o + 1] = h1;
                hx = h0; hy = h1;
            }
        }
        float gx, gy;
        if (mode < 5) {
            float d  = 0.5f * (hx - hy);
            float rr = rsqrtf(d * d + 1e-5f);
            gx =  d * rr * gw0 + gb0;
            gy = -d * rr * gw1 + gb1;
        } else {
            gx = hx; gy = hy;
        }
        hsh[lr * 66 + 1 + 2 * lane] = gx;
        hsh[lr * 66 + 2 + 2 * lane] = gy;
        if (lane == 0) hsh[lr * 66] = (mode < 5) ? tval : 0.f;
    }
    __syncthreads();

    // Phase 2: tiled dense with packed f32x2 FMA, 96 rows = 16 ty-slots x 6
    int ty = tid >> 4, tx = tid & 15;
    int c0 = tx * 4;
    ull b01 = pk2(bsh[c0], bsh[c0 + 1]), b23 = pk2(bsh[c0 + 2], bsh[c0 + 3]);
    ull a01[6], a23[6];
#pragma unroll
    for (int i = 0; i < 6; i++) { a01[i] = b01; a23[i] = b23; }
    for (int k = 0; k < 65; k++) {
        float4 w4 = *(const float4*)&Wsh[k * CH + c0];
        ull w01 = pk2(w4.x, w4.y), w23 = pk2(w4.z, w4.w);
#pragma unroll
        for (int i = 0; i < 6; i++) {
            float a = hsh[(ty + 16 * i) * 66 + k];
            ull aa = pk2(a, a);
            a01[i] = fma2(aa, w01, a01[i]);
            a23[i] = fma2(aa, w23, a23[i]);
        }
    }
    float* sout = (mode < 5) ? g_s[1 - pin] : g_sf;
#pragma unroll
    for (int i = 0; i < 6; i++) {
        int nd = base + ty + 16 * i;
        if (nd < NN) {
            float v0, v1, v2, v3;
            upk2(a01[i], v0, v1); upk2(a23[i], v2, v3);
            *(float4*)&sout[nd * CH + c0] = make_float4(v0, v1, v2, v3);
        }
    }
}

// ============ final SpMM (40 cols, fp32 source) + log_softmax ============
__global__ void k_spmm40(float* __restrict__ out) {
    int row = (blockIdx.x * blockDim.x + threadIdx.x) >> 5;
    if (row >= NN) return;
    int lane = threadIdx.x & 31;
    int beg = g_rowptr[row], end = g_rowptr[row + 1];
    float ax = 0.f, ay = 0.f;
    for (int j = beg; j < end; j += 32) {
        int idx = j + lane;
        int sv = 0; float wv = 0.f;
        if (idx < end) { sv = g_csrsrc[idx]; wv = g_csrw[idx]; }
        int cnt4 = (min(32, end - j) + 3) & ~3;
        for (int q = 0; q < cnt4; q += 4) {
            int   s0 = __shfl_sync(0xffffffffu, sv, q);
            int   s1 = __shfl_sync(0xffffffffu, sv, q + 1);
            int   s2 = __shfl_sync(0xffffffffu, sv, q + 2);
            int   s3 = __shfl_sync(0xffffffffu, sv, q + 3);
            float w0 = __shfl_sync(0xffffffffu, wv, q);
            float w1 = __shfl_sync(0xffffffffu, wv, q + 1);
            float w2 = __shfl_sync(0xffffffffu, wv, q + 2);
            float w3 = __shfl_sync(0xffffffffu, wv, q + 3);
            if (lane < 20) {
                float2 r0 = *(const float2*)&g_sf[s0 * CH + 2 * lane];
                float2 r1 = *(const float2*)&g_sf[s1 * CH + 2 * lane];
                float2 r2 = *(const float2*)&g_sf[s2 * CH + 2 * lane];
                float2 r3 = *(const float2*)&g_sf[s3 * CH + 2 * lane];
                ax += w0 * r0.x; ay += w0 * r0.y;
                ax += w1 * r1.x; ay += w1 * r1.y;
                ax += w2 * r2.x; ay += w2 * r2.y;
                ax += w3 * r3.x; ay += w3 * r3.y;
            }
        }
    }
    float NEG_INF = __int_as_float(0xff800000);
    float m = (lane < 20) ? fmaxf(ax, ay) : NEG_INF;
#pragma unroll
    for (int o = 16; o; o >>= 1) m = fmaxf(m, __shfl_xor_sync(0xffffffffu, m, o));
    float se = (lane < 20) ? (expf(ax - m) + expf(ay - m)) : 0.f;
#pragma unroll
    for (int o = 16; o; o >>= 1) se += __shfl_xor_sync(0xffffffffu, se, o);
    float lse = m + logf(se);
    if (lane < 20) {
        out[row * NC + 2 * lane]     = ax - lse;
        out[row * NC + 2 * lane + 1] = ay - lse;
    }
}

// =============================== driver ===============================
extern "C" void kernel_launch(void* const* d_in, const int* in_sizes, int n_in,
                              void* d_out, int out_size) {
    const float* x   = (const float*)d_in[0];
    const int*   src = (const int*)  d_in[1];
    const int*   tgt = (const int*)  d_in[2];
    const float* mw  = (const float*)d_in[3];
    const float* W0  = (const float*)d_in[4];
    const float* b0  = (const float*)d_in[5];
    const float* gnw = (const float*)d_in[6];
    const float* gnb = (const float*)d_in[7];
    const float* W1  = (const float*)d_in[8];
    const float* b1  = (const float*)d_in[9];
    const float* W2  = (const float*)d_in[10];
    const float* b2  = (const float*)d_in[11];
    float* out = (float*)d_out;
    (void)in_sizes; (void)n_in; (void)out_size;

    const int FUB = (NN + NPB - 1) / NPB;
    const int SPB = (NN * 32 + 255) / 256;

    k_hist<<<FILLB, 256>>>(tgt);                               // idx 0
    k_scan_all<<<NB_SCAN, SCAN_B>>>();                         // idx 1
    k_prep<<<FILLB + MMB0, 256>>>(x, src, tgt, mw, W0, b0);    // idx 2

    int p = 0;
    // idx 3 — ncu capture slot: fused [spmm0 + first-eval dense]
    k_fused<<<FUB, 256>>>(0, p, 0.f, 0.f, 0.0f, W1, b1, gnw, gnb, W2, b2);
    p ^= 1;

    const float dt = 0.25f;
    for (int st = 0; st < 4; st++) {
        float t0 = st * dt;
        k_fused<<<FUB, 256>>>(1, p, dt / 6.f, dt * 0.5f, t0 + dt * 0.5f, W1, b1, gnw, gnb, W2, b2); p ^= 1;
        k_fused<<<FUB, 256>>>(2, p, dt / 3.f, dt * 0.5f, t0 + dt * 0.5f, W1, b1, gnw, gnb, W2, b2); p ^= 1;
        k_fused<<<FUB, 256>>>(2, p, dt / 3.f, dt,        t0 + dt,        W1, b1, gnw, gnb, W2, b2); p ^= 1;
        int m4 = (st == 3) ? 5 : 4;
        k_fused<<<FUB, 256>>>(m4, p, dt / 6.f, 0.f, (st + 1) * dt, W1, b1, gnw, gnb, W2, b2); p ^= 1;
    }

    k_spmm40<<<SPB, 256>>>(out);
}

// round 12
// speedup vs baseline: 1.1812x; 1.0870x over previous
#include <cuda_runtime.h>
#include <cuda_fp16.h>
#include <math.h>

#define NN 100000
#define EE 1600000
#define CH 64      // NHID
#define NF 128     // NFEAT
#define NC 40      // NCLASS
#define SCAN_B 1024
#define NB_SCAN ((NN + SCAN_B - 1) / SCAN_B)   // 98
#define NPB 96     // rows per fused block
#define MMR 96     // rows per mm0 block
#define FILLB ((EE + 255) / 256)               // 6250
#define MMB0  ((NN + MMR - 1) / MMR)           // 1042

typedef unsigned long long ull;

// ---- packed f32x2 helpers (sm_10x FFMA2; PTX-only) ----
__device__ __forceinline__ ull pk2(float lo, float hi) {
    ull r;
    asm("mov.b64 %0, {%1, %2};" : "=l"(r) : "r"(__float_as_uint(lo)), "r"(__float_as_uint(hi)));
    return r;
}
__device__ __forceinline__ void upk2(ull v, float& lo, float& hi) {
    unsigned a, b;
    asm("mov.b64 {%0, %1}, %2;" : "=r"(a), "=r"(b) : "l"(v));
    lo = __uint_as_float(a); hi = __uint_as_float(b);
}
__device__ __forceinline__ ull fma2(ull a, ull b, ull c) {
    ull d;
    asm("fma.rn.f32x2 %0, %1, %2, %3;" : "=l"(d) : "l"(a), "l"(b), "l"(c));
    return d;
}

// ---- scratch (static device globals; no allocation) ----
__device__ float  g_h[NN * CH];
__device__ float  g_acc[NN * CH];
__device__ float  g_s[2][NN * CH];    // fp32 double-buffered gather source
__device__ float  g_sf[NN * CH];      // fp32 final-logits buffer
__device__ int    g_rowptr[NN + 1];
__device__ int    g_cursor[NN];
__device__ int    g_cnt[NN];          // zero at module load; re-zeroed by k_prep each call
__device__ int    g_csrsrc[EE];
__device__ float  g_csrw[EE];

// ============================ CSR build ============================
__global__ void k_hist(const int* __restrict__ tgt) {
    int e = blockIdx.x * blockDim.x + threadIdx.x;
    if (e < EE) atomicAdd(&g_cnt[tgt[e]], 1);
}

__global__ void k_scan_all() {
    __shared__ int sh[SCAN_B];
    __shared__ int soff;
    int b = blockIdx.x, tid = threadIdx.x;
    int base = b * SCAN_B;
    int acc = 0;
    for (int j = tid; j < base; j += SCAN_B) acc += g_cnt[j];
    sh[tid] = acc;
    __syncthreads();
    for (int d = SCAN_B / 2; d; d >>= 1) {
        if (tid < d) sh[tid] += sh[tid + d];
        __syncthreads();
    }
    if (tid == 0) soff = sh[0];
    __syncthreads();
    int i = base + tid;
    int v = (i < NN) ? g_cnt[i] : 0;
    sh[tid] = v;
    __syncthreads();
    for (int d = 1; d < SCAN_B; d <<= 1) {
        int t = (tid >= d) ? sh[tid - d] : 0;
        __syncthreads();
        sh[tid] += t;
        __syncthreads();
    }
    if (i < NN) {
        int ex = soff + sh[tid] - v;
        g_rowptr[i] = ex;
        g_cursor[i] = ex;
    }
    if (b == NB_SCAN - 1 && tid == SCAN_B - 1) g_rowptr[NN] = soff + sh[tid];
}

// ================= prep: CSR fill + mm0 dense + cnt re-zero (merged) =================
__global__ void k_prep(const float* __restrict__ x,
                       const int* __restrict__ src, const int* __restrict__ tgt,
                       const float* __restrict__ w,
                       const float* __restrict__ W0, const float* __restrict__ b0) {
    __shared__ float Wsh[NF * CH];   // 32KB (only used by mm0 blocks)
    int tid = threadIdx.x;

    if (blockIdx.x < FILLB) {
        int e = blockIdx.x * 256 + tid;
        if (e < EE) {
            int slot = atomicAdd(&g_cursor[tgt[e]], 1);
            g_csrsrc[slot] = src[e];
            g_csrw[slot]  = w[e];
        }
        return;
    }

    int mb = blockIdx.x - FILLB;     // 0..MMB0-1
    for (int i = mb * 256 + tid; i < NN; i += MMB0 * 256) g_cnt[i] = 0;

    for (int i = tid; i < NF * CH; i += 256) Wsh[i] = W0[i];
    __syncthreads();

    int base = mb * MMR;
    int ty = tid >> 4, tx = tid & 15;
    int c0 = tx * 4;

    ull a01[6], a23[6];
    ull b01 = pk2(b0[c0], b0[c0 + 1]), b23 = pk2(b0[c0 + 2], b0[c0 + 3]);
#pragma unroll
    for (int i = 0; i < 6; i++) { a01[i] = b01; a23[i] = b23; }

    const float* xr[6];
#pragma unroll
    for (int i = 0; i < 6; i++) {
        int nd = base + ty + 16 * i;
        if (nd > NN - 1) nd = NN - 1;
        xr[i] = x + (size_t)nd * NF;
    }
    for (int k = 0; k < NF; k += 4) {
        float4 a4[6];
#pragma unroll
        for (int i = 0; i < 6; i++) a4[i] = *(const float4*)&xr[i][k];
#pragma unroll
        for (int kk = 0; kk < 4; kk++) {
            float4 w4 = *(const float4*)&Wsh[(k + kk) * CH + c0];
            ull w01 = pk2(w4.x, w4.y), w23 = pk2(w4.z, w4.w);
#pragma unroll
            for (int i = 0; i < 6; i++) {
                float a = (kk == 0) ? a4[i].x : (kk == 1) ? a4[i].y : (kk == 2) ? a4[i].z : a4[i].w;
                ull aa = pk2(a, a);
                a01[i] = fma2(aa, w01, a01[i]);
                a23[i] = fma2(aa, w23, a23[i]);
            }
        }
    }
#pragma unroll
    for (int i = 0; i < 6; i++) {
        int nd = base + ty + 16 * i;
        if (nd < NN) {
            float v0, v1, v2, v3;
            upk2(a01[i], v0, v1); upk2(a23[i], v2, v3);
            *(float4*)&g_s[0][nd * CH + c0] = make_float4(v0, v1, v2, v3);
        }
    }
}

// ================= fused SpMM + RK4 bookkeeping + groupnorm + dense =================
// Phase 1: half-warp float4 gather — two edges per LDG.128 (lanes (hw,l):
// edge q+2u+hw, cols 4l..4l+3), half the LDG+SHFL issue of the R6 body.
// Row sums combined via shfl_xor(16); epilogue on lane<16 with float4 ops.
// t-column folded into bias (bsh = b1 + t*W1[0]); Wsh holds W1 rows 1..64.
//   mode 0: h = k, store g_h;                heff = h
//   mode 1: acc  = wk*k;                     heff = h + ch*k
//   mode 2: acc += wk*k;                     heff = h + ch*k
//   mode 4: h  += acc + wk*k, store g_h;     heff = h_new
//   mode 5: as 4, but phase 2 uses W2, no groupnorm, out to g_sf
__global__ void __launch_bounds__(256)
k_fused(int mode, int pin, float wk, float ch, float tval,
        const float* __restrict__ W1, const float* __restrict__ b1,
        const float* __restrict__ gnw, const float* __restrict__ gnb,
        const float* __restrict__ W2, const float* __restrict__ b2) {
    __shared__ float Wsh[64 * CH];     // 16 KB  (rows 1..64 of W1, or W2 zero-padded)
    __shared__ float bsh[CH];          // b1 + t*W1[0]  (or b2 padded)
    __shared__ float hsh[NPB * 64];    // 24 KB, float4-aligned rows

    const float* __restrict__ sin = g_s[pin];

    int tid = threadIdx.x;
    if (mode < 5) {
        for (int i = tid; i < 64 * CH; i += 256) {
            int r = i >> 6, c = i & 63;
            Wsh[i] = W1[(r + 1) * CH + c];
        }
        if (tid < CH) bsh[tid] = b1[tid] + tval * W1[tid];   // fold t row
    } else {
        for (int i = tid; i < 64 * CH; i += 256) {
            int r = i >> 6, c = i & 63;
            Wsh[i] = (c < NC) ? W2[r * NC + c] : 0.f;
        }
        if (tid < CH) bsh[tid] = (tid < NC) ? b2[tid] : 0.f;
    }

    int wid = tid >> 5, lane = tid & 31;
    int hw = lane >> 4, l = lane & 15;
    int base = blockIdx.x * NPB;

    float4 gw4 = make_float4(0.f, 0.f, 0.f, 0.f), gb4 = gw4;
    if (mode < 5) {
        gw4 = *(const float4*)&gnw[4 * l];
        gb4 = *(const float4*)&gnb[4 * l];
    }

    // Phase 1: each warp handles 12 rows
    for (int r = 0; r < NPB / 8; r++) {
        int lr  = wid * (NPB / 8) + r;
        int row = base + lr;
        float4 a4 = make_float4(0.f, 0.f, 0.f, 0.f);
        if (row < NN) {
            int beg = g_rowptr[row], end = g_rowptr[row + 1];
            for (int j = beg; j < end; j += 32) {
                int idx = j + lane;
                int sv = 0; float wv = 0.f;
                if (idx < end) { sv = g_csrsrc[idx]; wv = g_csrw[idx]; }
                int cnt8 = (min(32, end - j) + 7) & ~7;   // pad; dummy lanes sv=0, wv=0
                for (int q = 0; q < cnt8; q += 8) {
                    int ss[4]; float ww[4];
#pragma unroll
                    for (int u = 0; u < 4; u++) {
                        ss[u] = __shfl_sync(0xffffffffu, sv, q + 2 * u + hw);
                        ww[u] = __shfl_sync(0xffffffffu, wv, q + 2 * u + hw);
                    }
                    float4 rr[4];
#pragma unroll
                    for (int u = 0; u < 4; u++)
                        rr[u] = *(const float4*)&sin[ss[u] * CH + 4 * l];
#pragma unroll
                    for (int u = 0; u < 4; u++) {
                        a4.x += ww[u] * rr[u].x;
                        a4.y += ww[u] * rr[u].y;
                        a4.z += ww[u] * rr[u].z;
                        a4.w += ww[u] * rr[u].w;
                    }
                }
            }
        }
        // combine the two half-warps (each holds one edge-parity partial sum)
        a4.x += __shfl_xor_sync(0xffffffffu, a4.x, 16);
        a4.y += __shfl_xor_sync(0xffffffffu, a4.y, 16);
        a4.z += __shfl_xor_sync(0xffffffffu, a4.z, 16);
        a4.w += __shfl_xor_sync(0xffffffffu, a4.w, 16);

        if (row < NN && hw == 0) {
            float vx = fmaxf(a4.x, 0.f), vy = fmaxf(a4.y, 0.f);
            float vz = fmaxf(a4.z, 0.f), vw = fmaxf(a4.w, 0.f);
            int o = row * CH + 4 * l;
            float4 hv;
            if (mode == 0) {
                hv = make_float4(vx, vy, vz, vw);
                *(float4*)&g_h[o] = hv;
            } else if (mode == 1) {
                float4 h4 = *(const float4*)&g_h[o];
                *(float4*)&g_acc[o] = make_float4(wk * vx, wk * vy, wk * vz, wk * vw);
                hv = make_float4(h4.x + ch * vx, h4.y + ch * vy, h4.z + ch * vz, h4.w + ch * vw);
            } else if (mode == 2) {
                float4 h4 = *(const float4*)&g_h[o];
                float4 ac = *(const float4*)&g_acc[o];
                *(float4*)&g_acc[o] = make_float4(ac.x + wk * vx, ac.y + wk * vy,
                                                  ac.z + wk * vz, ac.w + wk * vw);
                hv = make_float4(h4.x + ch * vx, h4.y + ch * vy, h4.z + ch * vz, h4.w + ch * vw);
            } else {  // 4 or 5: k4 state update
                float4 h4 = *(const float4*)&g_h[o];
                float4 ac = *(const float4*)&g_acc[o];
                hv = make_float4(h4.x + ac.x + wk * vx, h4.y + ac.y + wk * vy,
                                 h4.z + ac.z + wk * vz, h4.w + ac.w + wk * vw);
                *(float4*)&g_h[o] = hv;
            }
            float4 gv;
            if (mode < 5) {
                float d0 = 0.5f * (hv.x - hv.y);
                float r0 = rsqrtf(d0 * d0 + 1e-5f);
                float d1 = 0.5f * (hv.z - hv.w);
                float r1 = rsqrtf(d1 * d1 + 1e-5f);
                gv.x =  d0 * r0 * gw4.x + gb4.x;
                gv.y = -d0 * r0 * gw4.y + gb4.y;
                gv.z =  d1 * r1 * gw4.z + gb4.z;
                gv.w = -d1 * r1 * gw4.w + gb4.w;
            } else {
                gv = hv;
            }
            *(float4*)&hsh[lr * 64 + 4 * l] = gv;
        }
    }
    __syncthreads();

    // Phase 2: tiled dense with packed f32x2 FMA, 96 rows = 16 ty-slots x 6, k=0..63
    int ty = tid >> 4, tx = tid & 15;
    int c0 = tx * 4;
    ull b01 = pk2(bsh[c0], bsh[c0 + 1]), b23 = pk2(bsh[c0 + 2], bsh[c0 + 3]);
    ull a01[6], a23[6];
#pragma unroll
    for (int i = 0; i < 6; i++) { a01[i] = b01; a23[i] = b23; }
    for (int k = 0; k < 64; k++) {
        float4 w4 = *(const float4*)&Wsh[k * CH + c0];
        ull w01 = pk2(w4.x, w4.y), w23 = pk2(w4.z, w4.w);
#pragma unroll
        for (int i = 0; i < 6; i++) {
            float a = hsh[(ty + 16 * i) * 64 + k];
            ull aa = pk2(a, a);
            a01[i] = fma2(aa, w01, a01[i]);
            a23[i] = fma2(aa, w23, a23[i]);
        }
    }
    float* sout = (mode < 5) ? g_s[1 - pin] : g_sf;
#pragma unroll
    for (int i = 0; i < 6; i++) {
        int nd = base + ty + 16 * i;
        if (nd < NN) {
            float v0, v1, v2, v3;
            upk2(a01[i], v0, v1); upk2(a23[i], v2, v3);
            *(float4*)&sout[nd * CH + c0] = make_float4(v0, v1, v2, v3);
        }
    }
}

// ============ final SpMM (40 cols, fp32 source) + log_softmax ============
__global__ void k_spmm40(float* __restrict__ out) {
    int row = (blockIdx.x * blockDim.x + threadIdx.x) >> 5;
    if (row >= NN) return;
    int lane = threadIdx.x & 31;
    int beg = g_rowptr[row], end = g_rowptr[row + 1];
    float ax = 0.f, ay = 0.f;
    for (int j = beg; j < end; j += 32) {
        int idx = j + lane;
        int sv = 0; float wv = 0.f;
        if (idx < end) { sv = g_csrsrc[idx]; wv = g_csrw[idx]; }
        int cnt4 = (min(32, end - j) + 3) & ~3;
        for (int q = 0; q < cnt4; q += 4) {
            int   s0 = __shfl_sync(0xffffffffu, sv, q);
            int   s1 = __shfl_sync(0xffffffffu, sv, q + 1);
            int   s2 = __shfl_sync(0xffffffffu, sv, q + 2);
            int   s3 = __shfl_sync(0xffffffffu, sv, q + 3);
            float w0 = __shfl_sync(0xffffffffu, wv, q);
            float w1 = __shfl_sync(0xffffffffu, wv, q + 1);
            float w2 = __shfl_sync(0xffffffffu, wv, q + 2);
            float w3 = __shfl_sync(0xffffffffu, wv, q + 3);
            if (lane < 20) {
                float2 r0 = *(const float2*)&g_sf[s0 * CH + 2 * lane];
                float2 r1 = *(const float2*)&g_sf[s1 * CH + 2 * lane];
                float2 r2 = *(const float2*)&g_sf[s2 * CH + 2 * lane];
                float2 r3 = *(const float2*)&g_sf[s3 * CH + 2 * lane];
                ax += w0 * r0.x; ay += w0 * r0.y;
                ax += w1 * r1.x; ay += w1 * r1.y;
                ax += w2 * r2.x; ay += w2 * r2.y;
                ax += w3 * r3.x; ay += w3 * r3.y;
            }
        }
    }
    float NEG_INF = __int_as_float(0xff800000);
    float m = (lane < 20) ? fmaxf(ax, ay) : NEG_INF;
#pragma unroll
    for (int o = 16; o; o >>= 1) m = fmaxf(m, __shfl_xor_sync(0xffffffffu, m, o));
    float se = (lane < 20) ? (expf(ax - m) + expf(ay - m)) : 0.f;
#pragma unroll
    for (int o = 16; o; o >>= 1) se += __shfl_xor_sync(0xffffffffu, se, o);
    float lse = m + logf(se);
    if (lane < 20) {
        out[row * NC + 2 * lane]     = ax - lse;
        out[row * NC + 2 * lane + 1] = ay - lse;
    }
}

// =============================== driver ===============================
extern "C" void kernel_launch(void* const* d_in, const int* in_sizes, int n_in,
                              void* d_out, int out_size) {
    const float* x   = (const float*)d_in[0];
    const int*   src = (const int*)  d_in[1];
    const int*   tgt = (const int*)  d_in[2];
    const float* mw  = (const float*)d_in[3];
    const float* W0  = (const float*)d_in[4];
    const float* b0  = (const float*)d_in[5];
    const float* gnw = (const float*)d_in[6];
    const float* gnb = (const float*)d_in[7];
    const float* W1  = (const float*)d_in[8];
    const float* b1  = (const float*)d_in[9];
    const float* W2  = (const float*)d_in[10];
    const float* b2  = (const float*)d_in[11];
    float* out = (float*)d_out;
    (void)in_sizes; (void)n_in; (void)out_size;

    const int FUB = (NN + NPB - 1) / NPB;
    const int SPB = (NN * 32 + 255) / 256;

    k_hist<<<FILLB, 256>>>(tgt);                               // idx 0
    k_scan_all<<<NB_SCAN, SCAN_B>>>();                         // idx 1
    k_prep<<<FILLB + MMB0, 256>>>(x, src, tgt, mw, W0, b0);    // idx 2

    int p = 0;
    // idx 3 — ncu capture slot: fused [spmm0 + first-eval dense] at t=0
    k_fused<<<FUB, 256>>>(0, p, 0.f, 0.f, 0.0f, W1, b1, gnw, gnb, W2, b2);
    p ^= 1;

    const float dt = 0.25f;
    for (int st = 0; st < 4; st++) {
        float t0 = st * dt;
        k_fused<<<FUB, 256>>>(1, p, dt / 6.f, dt * 0.5f, t0 + dt * 0.5f, W1, b1, gnw, gnb, W2, b2); p ^= 1;
        k_fused<<<FUB, 256>>>(2, p, dt / 3.f, dt * 0.5f, t0 + dt * 0.5f, W1, b1, gnw, gnb, W2, b2); p ^= 1;
        k_fused<<<FUB, 256>>>(2, p, dt / 3.f, dt,        t0 + dt,        W1, b1, gnw, gnb, W2, b2); p ^= 1;
        int m4 = (st == 3) ? 5 : 4;
        k_fused<<<FUB, 256>>>(m4, p, dt / 6.f, 0.f, (st + 1) * dt, W1, b1, gnw, gnb, W2, b2); p ^= 1;
    }

    k_spmm40<<<SPB, 256>>>(out);
}